// round 2
// baseline (speedup 1.0000x reference)
#include <cuda_runtime.h>

#define NB 8
#define SEQ 2048
#define DIN 512
#define DH 128
#define MTOT (NB*SEQ)

// Scratch (device globals: allocation-free rule)
__device__ float g_q[MTOT*DH];
__device__ float g_k[MTOT*DH];
__device__ float g_v[MTOT*DH];
__device__ float g_p[(size_t)NB*SEQ*SEQ];   // scores/probs, 128 MB

// ---------------------------------------------------------------------------
// Fused QKV projection: Out[m][n] = sum_k X[m][k] * W[k][n] + bias[n]
// M=16384, K=512, N=128. Tile: BM=128, BN=128(full), BK=32. 256 thr, 8x8/thr.
// A is transposed into smem [k][m] with XOR swizzle: phys = m ^ ((k>>2 & 15)<<2)
// -> conflict-free scalar stores and conflict-free float4 compute loads.
// ---------------------------------------------------------------------------
__global__ __launch_bounds__(256, 2) void proj_kernel(
    const float* __restrict__ x0, const float* __restrict__ x1, const float* __restrict__ x2,
    const float* __restrict__ w0, const float* __restrict__ w1, const float* __restrict__ w2,
    const float* __restrict__ b0, const float* __restrict__ b1, const float* __restrict__ b2)
{
    int sel = blockIdx.y;
    const float* X    = sel == 0 ? x0 : (sel == 1 ? x1 : x2);
    const float* W    = sel == 0 ? w0 : (sel == 1 ? w1 : w2);
    const float* bias = sel == 0 ? b0 : (sel == 1 ? b1 : b2);
    float*       Out  = sel == 0 ? g_q : (sel == 1 ? g_k : g_v);

    __shared__ float As[32][128];   // [k][m] swizzled
    __shared__ float Bs[32][DH];    // [k][n] direct

    int m0  = blockIdx.x * 128;
    int tid = threadIdx.x;
    int tr  = tid >> 4, tc = tid & 15;

    float acc[8][8];
    #pragma unroll
    for (int i = 0; i < 8; i++)
        #pragma unroll
        for (int j = 0; j < 8; j++) acc[i][j] = 0.f;

    for (int k0 = 0; k0 < DIN; k0 += 32) {
        // A tile: 128 rows x 32 k. 1024 float4 / 256 thr = 4 each.
        #pragma unroll
        for (int it = 0; it < 4; it++) {
            int idx = tid + it * 256;
            int r   = idx >> 3;        // m row 0..127
            int c4  = idx & 7;         // k-group 0..7
            float4 v = *(const float4*)(X + (size_t)(m0 + r) * DIN + k0 + c4 * 4);
            int pc  = r ^ (c4 << 2);
            int ks  = c4 * 4;
            As[ks + 0][pc] = v.x; As[ks + 1][pc] = v.y;
            As[ks + 2][pc] = v.z; As[ks + 3][pc] = v.w;
        }
        // B tile: 32 x 128. 1024 float4 / 256 = 4 each.
        #pragma unroll
        for (int it = 0; it < 4; it++) {
            int idx = tid + it * 256;
            int r   = idx >> 5;        // k 0..31
            int c4  = idx & 31;        // n-group
            *(float4*)&Bs[r][c4 * 4] =
                *(const float4*)(W + (size_t)(k0 + r) * DH + c4 * 4);
        }
        __syncthreads();
        #pragma unroll
        for (int kk = 0; kk < 32; kk++) {
            int C = kk & ~3;
            float a[8], bv[8];
            *(float4*)&a[0]  = *(const float4*)&As[kk][(tr * 4) ^ C];
            *(float4*)&a[4]  = *(const float4*)&As[kk][(64 + tr * 4) ^ C];
            *(float4*)&bv[0] = *(const float4*)&Bs[kk][tc * 4];
            *(float4*)&bv[4] = *(const float4*)&Bs[kk][64 + tc * 4];
            #pragma unroll
            for (int i = 0; i < 8; i++)
                #pragma unroll
                for (int j = 0; j < 8; j++)
                    acc[i][j] = fmaf(a[i], bv[j], acc[i][j]);
        }
        __syncthreads();
    }
    #pragma unroll
    for (int i = 0; i < 8; i++) {
        int m = m0 + (i < 4 ? tr * 4 + i : 64 + tr * 4 + (i - 4));
        #pragma unroll
        for (int jh = 0; jh < 2; jh++) {
            int c = (jh == 0) ? tc * 4 : 64 + tc * 4;
            float4 v;
            v.x = acc[i][jh * 4 + 0] + bias[c + 0];
            v.y = acc[i][jh * 4 + 1] + bias[c + 1];
            v.z = acc[i][jh * 4 + 2] + bias[c + 2];
            v.w = acc[i][jh * 4 + 3] + bias[c + 3];
            *(float4*)(Out + (size_t)m * DH + c) = v;
        }
    }
}

// ---------------------------------------------------------------------------
// scores[b][m][n] = scale * sum_d Q[b][m][d] * K[b][n][d]  (NT GEMM)
// BM=BN=128, BK=32 over DH=128. Both operands transposed+swizzled in smem.
// ---------------------------------------------------------------------------
__global__ __launch_bounds__(256, 2) void scores_kernel()
{
    __shared__ float Qs[32][128];
    __shared__ float Ks[32][128];

    int b  = blockIdx.z;
    int m0 = blockIdx.x * 128, n0 = blockIdx.y * 128;
    const float* Qb = g_q + (size_t)b * SEQ * DH;
    const float* Kb = g_k + (size_t)b * SEQ * DH;
    int tid = threadIdx.x, tr = tid >> 4, tc = tid & 15;

    float acc[8][8];
    #pragma unroll
    for (int i = 0; i < 8; i++)
        #pragma unroll
        for (int j = 0; j < 8; j++) acc[i][j] = 0.f;

    for (int k0 = 0; k0 < DH; k0 += 32) {
        #pragma unroll
        for (int it = 0; it < 4; it++) {
            int idx = tid + it * 256;
            int r   = idx >> 3;
            int c4  = idx & 7;
            int pc  = r ^ (c4 << 2);
            int ks  = c4 * 4;
            float4 v = *(const float4*)(Qb + (size_t)(m0 + r) * DH + k0 + c4 * 4);
            Qs[ks + 0][pc] = v.x; Qs[ks + 1][pc] = v.y;
            Qs[ks + 2][pc] = v.z; Qs[ks + 3][pc] = v.w;
            float4 w = *(const float4*)(Kb + (size_t)(n0 + r) * DH + k0 + c4 * 4);
            Ks[ks + 0][pc] = w.x; Ks[ks + 1][pc] = w.y;
            Ks[ks + 2][pc] = w.z; Ks[ks + 3][pc] = w.w;
        }
        __syncthreads();
        #pragma unroll
        for (int kk = 0; kk < 32; kk++) {
            int C = kk & ~3;
            float a[8], bv[8];
            *(float4*)&a[0]  = *(const float4*)&Qs[kk][(tr * 4) ^ C];
            *(float4*)&a[4]  = *(const float4*)&Qs[kk][(64 + tr * 4) ^ C];
            *(float4*)&bv[0] = *(const float4*)&Ks[kk][(tc * 4) ^ C];
            *(float4*)&bv[4] = *(const float4*)&Ks[kk][(64 + tc * 4) ^ C];
            #pragma unroll
            for (int i = 0; i < 8; i++)
                #pragma unroll
                for (int j = 0; j < 8; j++)
                    acc[i][j] = fmaf(a[i], bv[j], acc[i][j]);
        }
        __syncthreads();
    }

    const float scale = 0.08838834764831845f;  // 1/sqrt(128)
    float* Pb = g_p + (size_t)b * SEQ * SEQ;
    #pragma unroll
    for (int i = 0; i < 8; i++) {
        int m = m0 + (i < 4 ? tr * 4 + i : 64 + tr * 4 + (i - 4));
        #pragma unroll
        for (int jh = 0; jh < 2; jh++) {
            int c = n0 + ((jh == 0) ? tc * 4 : 64 + tc * 4);
            float4 v;
            v.x = acc[i][jh * 4 + 0] * scale;
            v.y = acc[i][jh * 4 + 1] * scale;
            v.z = acc[i][jh * 4 + 2] * scale;
            v.w = acc[i][jh * 4 + 3] * scale;
            *(float4*)(Pb + (size_t)m * SEQ + c) = v;
        }
    }
}

// ---------------------------------------------------------------------------
// Row softmax over g_p, in place. One block per row (16384 rows, 2048 cols).
// ---------------------------------------------------------------------------
__global__ __launch_bounds__(256) void softmax_kernel()
{
    size_t row = blockIdx.x;
    float* p   = g_p + row * (size_t)SEQ;
    int tid    = threadIdx.x;
    int wid    = tid >> 5, lane = tid & 31;

    float v[8];
    float mx = -1e30f;
    #pragma unroll
    for (int i = 0; i < 8; i++) { v[i] = p[tid + i * 256]; mx = fmaxf(mx, v[i]); }
    #pragma unroll
    for (int o = 16; o > 0; o >>= 1) mx = fmaxf(mx, __shfl_xor_sync(0xffffffffu, mx, o));

    __shared__ float redm[8];
    __shared__ float reds[8];
    if (lane == 0) redm[wid] = mx;
    __syncthreads();
    #pragma unroll
    for (int w = 0; w < 8; w++) mx = fmaxf(mx, redm[w]);

    float s = 0.f;
    #pragma unroll
    for (int i = 0; i < 8; i++) { v[i] = __expf(v[i] - mx); s += v[i]; }
    #pragma unroll
    for (int o = 16; o > 0; o >>= 1) s += __shfl_xor_sync(0xffffffffu, s, o);
    if (lane == 0) reds[wid] = s;
    __syncthreads();
    s = 0.f;
    #pragma unroll
    for (int w = 0; w < 8; w++) s += reds[w];

    float inv = 1.0f / s;
    #pragma unroll
    for (int i = 0; i < 8; i++) p[tid + i * 256] = v[i] * inv;
}

// ---------------------------------------------------------------------------
// Out[b][m][n] = sum_k P[b][m][k] * V[b][k][n].  M=2048/batch, N=128, K=2048.
// Same tile engine as proj (A transposed+swizzled, B direct).
// ---------------------------------------------------------------------------
__global__ __launch_bounds__(256, 2) void pv_kernel(float* __restrict__ Out)
{
    __shared__ float As[32][128];
    __shared__ float Bs[32][DH];

    int b  = blockIdx.z;
    int m0 = blockIdx.x * 128;
    const float* Pb = g_p + (size_t)b * SEQ * SEQ;
    const float* Vb = g_v + (size_t)b * SEQ * DH;
    float*       Ob = Out + (size_t)b * SEQ * DH;
    int tid = threadIdx.x, tr = tid >> 4, tc = tid & 15;

    float acc[8][8];
    #pragma unroll
    for (int i = 0; i < 8; i++)
        #pragma unroll
        for (int j = 0; j < 8; j++) acc[i][j] = 0.f;

    for (int k0 = 0; k0 < SEQ; k0 += 32) {
        #pragma unroll
        for (int it = 0; it < 4; it++) {
            int idx = tid + it * 256;
            int r   = idx >> 3;
            int c4  = idx & 7;
            int pc  = r ^ (c4 << 2);
            int ks  = c4 * 4;
            float4 v = *(const float4*)(Pb + (size_t)(m0 + r) * SEQ + k0 + c4 * 4);
            As[ks + 0][pc] = v.x; As[ks + 1][pc] = v.y;
            As[ks + 2][pc] = v.z; As[ks + 3][pc] = v.w;
        }
        #pragma unroll
        for (int it = 0; it < 4; it++) {
            int idx = tid + it * 256;
            int r   = idx >> 5;
            int c4  = idx & 31;
            *(float4*)&Bs[r][c4 * 4] =
                *(const float4*)(Vb + (size_t)(k0 + r) * DH + c4 * 4);
        }
        __syncthreads();
        #pragma unroll
        for (int kk = 0; kk < 32; kk++) {
            int C = kk & ~3;
            float a[8], bv[8];
            *(float4*)&a[0]  = *(const float4*)&As[kk][(tr * 4) ^ C];
            *(float4*)&a[4]  = *(const float4*)&As[kk][(64 + tr * 4) ^ C];
            *(float4*)&bv[0] = *(const float4*)&Bs[kk][tc * 4];
            *(float4*)&bv[4] = *(const float4*)&Bs[kk][64 + tc * 4];
            #pragma unroll
            for (int i = 0; i < 8; i++)
                #pragma unroll
                for (int j = 0; j < 8; j++)
                    acc[i][j] = fmaf(a[i], bv[j], acc[i][j]);
        }
        __syncthreads();
    }
    #pragma unroll
    for (int i = 0; i < 8; i++) {
        int m = m0 + (i < 4 ? tr * 4 + i : 64 + tr * 4 + (i - 4));
        #pragma unroll
        for (int jh = 0; jh < 2; jh++) {
            int c = (jh == 0) ? tc * 4 : 64 + tc * 4;
            float4 v;
            v.x = acc[i][jh * 4 + 0];
            v.y = acc[i][jh * 4 + 1];
            v.z = acc[i][jh * 4 + 2];
            v.w = acc[i][jh * 4 + 3];
            *(float4*)(Ob + (size_t)m * DH + c) = v;
        }
    }
}

extern "C" void kernel_launch(void* const* d_in, const int* in_sizes, int n_in,
                              void* d_out, int out_size)
{
    const float* q_in = (const float*)d_in[0];
    const float* k_in = (const float*)d_in[1];
    const float* v_in = (const float*)d_in[2];
    const float* Wq   = (const float*)d_in[3];
    const float* Wk   = (const float*)d_in[4];
    const float* Wv   = (const float*)d_in[5];
    const float* bq   = (const float*)d_in[6];
    const float* bk   = (const float*)d_in[7];
    const float* bv   = (const float*)d_in[8];
    float* out        = (float*)d_out;

    proj_kernel<<<dim3(MTOT / 128, 3), 256>>>(q_in, k_in, v_in, Wq, Wk, Wv, bq, bk, bv);
    scores_kernel<<<dim3(SEQ / 128, SEQ / 128, NB), 256>>>();
    softmax_kernel<<<MTOT, 256>>>();
    pv_kernel<<<dim3(SEQ / 128, 1, NB), 256>>>(out);
}

// round 4
// speedup vs baseline: 1.9184x; 1.9184x over previous
#include <cuda_runtime.h>
#include <cstdint>

#define NB 8
#define SEQ 2048
#define DIN 512
#define DH 128
#define MTOT (NB*SEQ)

#define ASTR 36    // A smem row stride (floats): conflict-free frag loads
#define BSTR 136   // B smem row stride (floats)

// Scratch (device globals: allocation-free rule)
__device__ float g_q[MTOT*DH];
__device__ float g_k[MTOT*DH];
__device__ float g_v[MTOT*DH];
__device__ float g_p[(size_t)NB*SEQ*SEQ];   // scores/probs, 128 MB

// ---------------------------------------------------------------------------
// tf32 helpers (baseline sm_80 ISA — no 'a'-suffix features)
// ---------------------------------------------------------------------------
__device__ __forceinline__ uint32_t f2tf(float x) {
    uint32_t u;
    asm("cvt.rna.tf32.f32 %0, %1;" : "=r"(u) : "f"(x));
    return u;
}
__device__ __forceinline__ void mma8(float* c, const uint32_t* a, const uint32_t* b) {
    asm volatile(
        "mma.sync.aligned.m16n8k8.row.col.f32.tf32.tf32.f32 "
        "{%0,%1,%2,%3}, {%4,%5,%6,%7}, {%8,%9}, {%0,%1,%2,%3};"
        : "+f"(c[0]), "+f"(c[1]), "+f"(c[2]), "+f"(c[3])
        : "r"(a[0]), "r"(a[1]), "r"(a[2]), "r"(a[3]), "r"(b[0]), "r"(b[1]));
}
// B-tile column swizzle: n' = n ^ (((k>>2)&7)<<2). Keeps float4 blocks intact,
// makes both transpose-stores and fragment loads bank-conflict-free.
__device__ __forceinline__ int bswz(int k, int n) {
    return n ^ (((k >> 2) & 7) << 2);
}

// One BK=32 compute stage. 8 warps as 4(m) x 2(n); warp tile 32x64.
__device__ __forceinline__ void mma_stage(const uint32_t* As, const uint32_t* Bs,
                                          int wm, int wn, int lane,
                                          float acc[2][8][4])
{
    int g = lane >> 2, t = lane & 3;
    #pragma unroll
    for (int s = 0; s < 4; s++) {
        int k8 = s * 8;
        uint32_t a[2][4], b[8][2];
        #pragma unroll
        for (int mt = 0; mt < 2; mt++) {
            int r = wm * 32 + mt * 16 + g;
            a[mt][0] = As[r * ASTR + k8 + t];
            a[mt][1] = As[(r + 8) * ASTR + k8 + t];
            a[mt][2] = As[r * ASTR + k8 + t + 4];
            a[mt][3] = As[(r + 8) * ASTR + k8 + t + 4];
        }
        #pragma unroll
        for (int nt = 0; nt < 8; nt++) {
            int c = wn * 64 + nt * 8 + g;
            b[nt][0] = Bs[(k8 + t) * BSTR + bswz(k8 + t, c)];
            b[nt][1] = Bs[(k8 + t + 4) * BSTR + bswz(k8 + t + 4, c)];
        }
        #pragma unroll
        for (int mt = 0; mt < 2; mt++)
            #pragma unroll
            for (int nt = 0; nt < 8; nt++)
                mma8(acc[mt][nt], a[mt], b[nt]);
    }
}

// ===========================================================================
// Fused QKV projection via tf32 MMA: Out = round_tf32(X*W + bias).
// M=16384 (128/block), N=128, K=512 (16 chunks of 32).
// ===========================================================================
__global__ __launch_bounds__(256, 2) void proj_kernel(
    const float* __restrict__ x0, const float* __restrict__ x1, const float* __restrict__ x2,
    const float* __restrict__ w0, const float* __restrict__ w1, const float* __restrict__ w2,
    const float* __restrict__ b0, const float* __restrict__ b1, const float* __restrict__ b2)
{
    __shared__ uint32_t As[128 * ASTR];
    __shared__ uint32_t Bs[32 * BSTR];

    int sel = blockIdx.y;
    const float* X    = sel == 0 ? x0 : (sel == 1 ? x1 : x2);
    const float* W    = sel == 0 ? w0 : (sel == 1 ? w1 : w2);
    const float* bias = sel == 0 ? b0 : (sel == 1 ? b1 : b2);
    float*       Out  = sel == 0 ? g_q : (sel == 1 ? g_k : g_v);

    int m0  = blockIdx.x * 128;
    int tid = threadIdx.x;
    int lane = tid & 31, wid = tid >> 5;
    int wm = wid & 3, wn = wid >> 2;

    float acc[2][8][4];
    #pragma unroll
    for (int i = 0; i < 2; i++)
        #pragma unroll
        for (int j = 0; j < 8; j++)
            #pragma unroll
            for (int q = 0; q < 4; q++) acc[i][j][q] = 0.f;

    for (int k0 = 0; k0 < DIN; k0 += 32) {
        #pragma unroll
        for (int it = 0; it < 4; it++) {      // A: 128x32
            int idx = tid + it * 256;
            int r = idx >> 3, c4 = idx & 7;
            float4 v = *(const float4*)(X + (size_t)(m0 + r) * DIN + k0 + c4 * 4);
            uint4 u = { f2tf(v.x), f2tf(v.y), f2tf(v.z), f2tf(v.w) };
            *(uint4*)&As[r * ASTR + c4 * 4] = u;
        }
        #pragma unroll
        for (int it = 0; it < 4; it++) {      // B: 32x128
            int idx = tid + it * 256;
            int r = idx >> 5, c4 = idx & 31;
            float4 v = *(const float4*)(W + (size_t)(k0 + r) * DH + c4 * 4);
            uint4 u = { f2tf(v.x), f2tf(v.y), f2tf(v.z), f2tf(v.w) };
            *(uint4*)&Bs[r * BSTR + bswz(r, c4 * 4)] = u;
        }
        __syncthreads();
        mma_stage(As, Bs, wm, wn, lane, acc);
        __syncthreads();
    }

    int g = lane >> 2, t = lane & 3;
    #pragma unroll
    for (int mt = 0; mt < 2; mt++) {
        int row = m0 + wm * 32 + mt * 16 + g;
        #pragma unroll
        for (int nt = 0; nt < 8; nt++) {
            int col = wn * 64 + nt * 8 + 2 * t;
            float bb0 = bias[col], bb1 = bias[col + 1];
            uint2 lo = { f2tf(acc[mt][nt][0] + bb0), f2tf(acc[mt][nt][1] + bb1) };
            uint2 hi = { f2tf(acc[mt][nt][2] + bb0), f2tf(acc[mt][nt][3] + bb1) };
            *(uint2*)(Out + (size_t)row * DH + col)       = lo;
            *(uint2*)(Out + (size_t)(row + 8) * DH + col) = hi;
        }
    }
}

// ===========================================================================
// scores[b][m][n] = scale * Q[m,:]·K[n,:]  via tf32 MMA (K tile transposed).
// ===========================================================================
__global__ __launch_bounds__(256, 2) void scores_kernel()
{
    __shared__ uint32_t As[128 * ASTR];
    __shared__ uint32_t Bs[32 * BSTR];

    int b  = blockIdx.z;
    int m0 = blockIdx.x * 128, n0 = blockIdx.y * 128;
    const uint32_t* Qb = (const uint32_t*)(g_q + (size_t)b * SEQ * DH);
    const uint32_t* Kb = (const uint32_t*)(g_k + (size_t)b * SEQ * DH);

    int tid = threadIdx.x;
    int lane = tid & 31, wid = tid >> 5;
    int wm = wid & 3, wn = wid >> 2;

    float acc[2][8][4];
    #pragma unroll
    for (int i = 0; i < 2; i++)
        #pragma unroll
        for (int j = 0; j < 8; j++)
            #pragma unroll
            for (int q = 0; q < 4; q++) acc[i][j][q] = 0.f;

    for (int k0 = 0; k0 < DH; k0 += 32) {
        #pragma unroll
        for (int it = 0; it < 4; it++) {      // A = Q tile 128x32 (pre-rounded)
            int idx = tid + it * 256;
            int r = idx >> 3, c4 = idx & 7;
            *(uint4*)&As[r * ASTR + c4 * 4] =
                *(const uint4*)(Qb + (size_t)(m0 + r) * DH + k0 + c4 * 4);
        }
        #pragma unroll
        for (int it = 0; it < 4; it++) {      // B = K^T: Bs[d][n] from K[n][d]
            int idx = tid + it * 256;
            int n = idx >> 3, c4 = idx & 7;
            uint4 u = *(const uint4*)(Kb + (size_t)(n0 + n) * DH + k0 + c4 * 4);
            int kk = c4 * 4;
            Bs[(kk + 0) * BSTR + bswz(kk + 0, n)] = u.x;
            Bs[(kk + 1) * BSTR + bswz(kk + 1, n)] = u.y;
            Bs[(kk + 2) * BSTR + bswz(kk + 2, n)] = u.z;
            Bs[(kk + 3) * BSTR + bswz(kk + 3, n)] = u.w;
        }
        __syncthreads();
        mma_stage(As, Bs, wm, wn, lane, acc);
        __syncthreads();
    }

    const float scale = 0.08838834764831845f;  // 1/sqrt(128)
    float* Pb = g_p + (size_t)b * SEQ * SEQ;
    int g = lane >> 2, t = lane & 3;
    #pragma unroll
    for (int mt = 0; mt < 2; mt++) {
        int row = m0 + wm * 32 + mt * 16 + g;
        #pragma unroll
        for (int nt = 0; nt < 8; nt++) {
            int col = n0 + wn * 64 + nt * 8 + 2 * t;
            float2 lo = { acc[mt][nt][0] * scale, acc[mt][nt][1] * scale };
            float2 hi = { acc[mt][nt][2] * scale, acc[mt][nt][3] * scale };
            *(float2*)(Pb + (size_t)row * SEQ + col)       = lo;
            *(float2*)(Pb + (size_t)(row + 8) * SEQ + col) = hi;
        }
    }
}

// ===========================================================================
// Row softmax over g_p, in place; output rounded to tf32 for the PV MMA.
// ===========================================================================
__global__ __launch_bounds__(256) void softmax_kernel()
{
    size_t row = blockIdx.x;
    float* p   = g_p + row * (size_t)SEQ;
    int tid    = threadIdx.x;
    int wid    = tid >> 5, lane = tid & 31;

    float4 va = ((const float4*)p)[tid];
    float4 vb = ((const float4*)p)[tid + 256];
    float mx = fmaxf(fmaxf(fmaxf(va.x, va.y), fmaxf(va.z, va.w)),
                     fmaxf(fmaxf(vb.x, vb.y), fmaxf(vb.z, vb.w)));
    #pragma unroll
    for (int o = 16; o > 0; o >>= 1) mx = fmaxf(mx, __shfl_xor_sync(0xffffffffu, mx, o));

    __shared__ float redm[8];
    __shared__ float reds[8];
    if (lane == 0) redm[wid] = mx;
    __syncthreads();
    #pragma unroll
    for (int w = 0; w < 8; w++) mx = fmaxf(mx, redm[w]);

    va.x = __expf(va.x - mx); va.y = __expf(va.y - mx);
    va.z = __expf(va.z - mx); va.w = __expf(va.w - mx);
    vb.x = __expf(vb.x - mx); vb.y = __expf(vb.y - mx);
    vb.z = __expf(vb.z - mx); vb.w = __expf(vb.w - mx);
    float s = (va.x + va.y + va.z + va.w) + (vb.x + vb.y + vb.z + vb.w);
    #pragma unroll
    for (int o = 16; o > 0; o >>= 1) s += __shfl_xor_sync(0xffffffffu, s, o);
    if (lane == 0) reds[wid] = s;
    __syncthreads();
    s = 0.f;
    #pragma unroll
    for (int w = 0; w < 8; w++) s += reds[w];

    float inv = 1.0f / s;
    uint4 oa = { f2tf(va.x * inv), f2tf(va.y * inv), f2tf(va.z * inv), f2tf(va.w * inv) };
    uint4 ob = { f2tf(vb.x * inv), f2tf(vb.y * inv), f2tf(vb.z * inv), f2tf(vb.w * inv) };
    ((uint4*)p)[tid]       = oa;
    ((uint4*)p)[tid + 256] = ob;
}

// ===========================================================================
// O[b][m][dh] = P[m,:]·V[:,dh]  via tf32 MMA.  K=2048, 64 chunks of 32.
// ===========================================================================
__global__ __launch_bounds__(256, 2) void pv_kernel(float* __restrict__ Out)
{
    __shared__ uint32_t As[128 * ASTR];
    __shared__ uint32_t Bs[32 * BSTR];

    int b  = blockIdx.y;
    int m0 = blockIdx.x * 128;
    const uint32_t* Pb = (const uint32_t*)(g_p + (size_t)b * SEQ * SEQ);
    const uint32_t* Vb = (const uint32_t*)(g_v + (size_t)b * SEQ * DH);
    float*          Ob = Out + (size_t)b * SEQ * DH;

    int tid = threadIdx.x;
    int lane = tid & 31, wid = tid >> 5;
    int wm = wid & 3, wn = wid >> 2;

    float acc[2][8][4];
    #pragma unroll
    for (int i = 0; i < 2; i++)
        #pragma unroll
        for (int j = 0; j < 8; j++)
            #pragma unroll
            for (int q = 0; q < 4; q++) acc[i][j][q] = 0.f;

    for (int k0 = 0; k0 < SEQ; k0 += 32) {
        #pragma unroll
        for (int it = 0; it < 4; it++) {      // A = P tile 128x32 (pre-rounded)
            int idx = tid + it * 256;
            int r = idx >> 3, c4 = idx & 7;
            *(uint4*)&As[r * ASTR + c4 * 4] =
                *(const uint4*)(Pb + (size_t)(m0 + r) * SEQ + k0 + c4 * 4);
        }
        #pragma unroll
        for (int it = 0; it < 4; it++) {      // B = V rows 32x128 (pre-rounded)
            int idx = tid + it * 256;
            int r = idx >> 5, c4 = idx & 31;
            *(uint4*)&Bs[r * BSTR + bswz(r, c4 * 4)] =
                *(const uint4*)(Vb + (size_t)(k0 + r) * DH + c4 * 4);
        }
        __syncthreads();
        mma_stage(As, Bs, wm, wn, lane, acc);
        __syncthreads();
    }

    int g = lane >> 2, t = lane & 3;
    #pragma unroll
    for (int mt = 0; mt < 2; mt++) {
        int row = m0 + wm * 32 + mt * 16 + g;
        #pragma unroll
        for (int nt = 0; nt < 8; nt++) {
            int col = wn * 64 + nt * 8 + 2 * t;
            float2 lo = { acc[mt][nt][0], acc[mt][nt][1] };
            float2 hi = { acc[mt][nt][2], acc[mt][nt][3] };
            *(float2*)(Ob + (size_t)row * DH + col)       = lo;
            *(float2*)(Ob + (size_t)(row + 8) * DH + col) = hi;
        }
    }
}

// ===========================================================================
extern "C" void kernel_launch(void* const* d_in, const int* in_sizes, int n_in,
                              void* d_out, int out_size)
{
    const float* q_in = (const float*)d_in[0];
    const float* k_in = (const float*)d_in[1];
    const float* v_in = (const float*)d_in[2];
    const float* Wq   = (const float*)d_in[3];
    const float* Wk   = (const float*)d_in[4];
    const float* Wv   = (const float*)d_in[5];
    const float* bq   = (const float*)d_in[6];
    const float* bk   = (const float*)d_in[7];
    const float* bv   = (const float*)d_in[8];
    float* out        = (float*)d_out;

    proj_kernel<<<dim3(MTOT / 128, 3), 256>>>(q_in, k_in, v_in, Wq, Wk, Wv, bq, bk, bv);
    scores_kernel<<<dim3(SEQ / 128, SEQ / 128, NB), 256>>>();
    softmax_kernel<<<MTOT, 256>>>();
    pv_kernel<<<dim3(SEQ / 128, NB), 256>>>(out);
}

// round 6
// speedup vs baseline: 2.4304x; 1.2669x over previous
#include <cuda_runtime.h>
#include <cstdint>

#define NB 8
#define SEQ 2048
#define DIN 512
#define DH 128
#define MTOT (NB*SEQ)
#define NTILES 16   // SEQ/128 column tiles per row

#define ASTR 36    // A smem row stride (floats): conflict-free frag loads
#define BSTR 136   // B smem row stride (floats)

// Scratch (device globals: allocation-free rule)
__device__ float g_q[MTOT*DH];
__device__ float g_k[MTOT*DH];
__device__ float g_v[MTOT*DH];
__device__ float g_p[(size_t)NB*SEQ*SEQ];   // raw scaled scores, 128 MB
__device__ float g_rmax[MTOT*NTILES];       // per (row, 128-col tile) max
__device__ float g_rsum[MTOT*NTILES];       // per (row, tile) sum exp(s - tilemax)
__device__ float g_rowm[MTOT];              // global row max
__device__ float g_rowinv[MTOT];            // 1 / global row sum

// ---------------------------------------------------------------------------
// tf32 helpers (baseline sm_80 ISA)
// ---------------------------------------------------------------------------
__device__ __forceinline__ uint32_t f2tf(float x) {
    uint32_t u;
    asm("cvt.rna.tf32.f32 %0, %1;" : "=r"(u) : "f"(x));
    return u;
}
__device__ __forceinline__ void mma8(float* c, const uint32_t* a, const uint32_t* b) {
    asm volatile(
        "mma.sync.aligned.m16n8k8.row.col.f32.tf32.tf32.f32 "
        "{%0,%1,%2,%3}, {%4,%5,%6,%7}, {%8,%9}, {%0,%1,%2,%3};"
        : "+f"(c[0]), "+f"(c[1]), "+f"(c[2]), "+f"(c[3])
        : "r"(a[0]), "r"(a[1]), "r"(a[2]), "r"(a[3]), "r"(b[0]), "r"(b[1]));
}
__device__ __forceinline__ int bswz(int k, int n) {
    return n ^ (((k >> 2) & 7) << 2);
}

// BK=32 stage, BM=128/BN=128: 8 warps as 4(m) x 2(n), warp tile 32x64.
__device__ __forceinline__ void mma_stage(const uint32_t* As, const uint32_t* Bs,
                                          int wm, int wn, int lane,
                                          float acc[2][8][4])
{
    int g = lane >> 2, t = lane & 3;
    #pragma unroll
    for (int s = 0; s < 4; s++) {
        int k8 = s * 8;
        uint32_t a[2][4], b[8][2];
        #pragma unroll
        for (int mt = 0; mt < 2; mt++) {
            int r = wm * 32 + mt * 16 + g;
            a[mt][0] = As[r * ASTR + k8 + t];
            a[mt][1] = As[(r + 8) * ASTR + k8 + t];
            a[mt][2] = As[r * ASTR + k8 + t + 4];
            a[mt][3] = As[(r + 8) * ASTR + k8 + t + 4];
        }
        #pragma unroll
        for (int nt = 0; nt < 8; nt++) {
            int c = wn * 64 + nt * 8 + g;
            b[nt][0] = Bs[(k8 + t) * BSTR + bswz(k8 + t, c)];
            b[nt][1] = Bs[(k8 + t + 4) * BSTR + bswz(k8 + t + 4, c)];
        }
        #pragma unroll
        for (int mt = 0; mt < 2; mt++)
            #pragma unroll
            for (int nt = 0; nt < 8; nt++)
                mma8(acc[mt][nt], a[mt], b[nt]);
    }
}

// BK=32 stage, BM=64/BN=128: 8 warps as 2(m) x 4(n), warp tile 32x32.
__device__ __forceinline__ void mma_stage64(const uint32_t* As, const uint32_t* Bs,
                                            int wm, int wn, int lane,
                                            float acc[2][4][4])
{
    int g = lane >> 2, t = lane & 3;
    #pragma unroll
    for (int s = 0; s < 4; s++) {
        int k8 = s * 8;
        uint32_t a[2][4], b[4][2];
        #pragma unroll
        for (int mt = 0; mt < 2; mt++) {
            int r = wm * 32 + mt * 16 + g;
            a[mt][0] = As[r * ASTR + k8 + t];
            a[mt][1] = As[(r + 8) * ASTR + k8 + t];
            a[mt][2] = As[r * ASTR + k8 + t + 4];
            a[mt][3] = As[(r + 8) * ASTR + k8 + t + 4];
        }
        #pragma unroll
        for (int nt = 0; nt < 4; nt++) {
            int c = wn * 32 + nt * 8 + g;
            b[nt][0] = Bs[(k8 + t) * BSTR + bswz(k8 + t, c)];
            b[nt][1] = Bs[(k8 + t + 4) * BSTR + bswz(k8 + t + 4, c)];
        }
        #pragma unroll
        for (int mt = 0; mt < 2; mt++)
            #pragma unroll
            for (int nt = 0; nt < 4; nt++)
                mma8(acc[mt][nt], a[mt], b[nt]);
    }
}

// ===========================================================================
// Fused QKV projection via tf32 MMA: Out = round_tf32(X*W + bias).
// ===========================================================================
__global__ __launch_bounds__(256, 2) void proj_kernel(
    const float* __restrict__ x0, const float* __restrict__ x1, const float* __restrict__ x2,
    const float* __restrict__ w0, const float* __restrict__ w1, const float* __restrict__ w2,
    const float* __restrict__ b0, const float* __restrict__ b1, const float* __restrict__ b2)
{
    __shared__ uint32_t As[128 * ASTR];
    __shared__ uint32_t Bs[32 * BSTR];

    int sel = blockIdx.y;
    const float* X    = sel == 0 ? x0 : (sel == 1 ? x1 : x2);
    const float* W    = sel == 0 ? w0 : (sel == 1 ? w1 : w2);
    const float* bias = sel == 0 ? b0 : (sel == 1 ? b1 : b2);
    float*       Out  = sel == 0 ? g_q : (sel == 1 ? g_k : g_v);

    int m0  = blockIdx.x * 128;
    int tid = threadIdx.x;
    int lane = tid & 31, wid = tid >> 5;
    int wm = wid & 3, wn = wid >> 2;

    float acc[2][8][4];
    #pragma unroll
    for (int i = 0; i < 2; i++)
        #pragma unroll
        for (int j = 0; j < 8; j++)
            #pragma unroll
            for (int q = 0; q < 4; q++) acc[i][j][q] = 0.f;

    for (int k0 = 0; k0 < DIN; k0 += 32) {
        #pragma unroll
        for (int it = 0; it < 4; it++) {
            int idx = tid + it * 256;
            int r = idx >> 3, c4 = idx & 7;
            float4 v = *(const float4*)(X + (size_t)(m0 + r) * DIN + k0 + c4 * 4);
            uint4 u = { f2tf(v.x), f2tf(v.y), f2tf(v.z), f2tf(v.w) };
            *(uint4*)&As[r * ASTR + c4 * 4] = u;
        }
        #pragma unroll
        for (int it = 0; it < 4; it++) {
            int idx = tid + it * 256;
            int r = idx >> 5, c4 = idx & 31;
            float4 v = *(const float4*)(W + (size_t)(k0 + r) * DH + c4 * 4);
            uint4 u = { f2tf(v.x), f2tf(v.y), f2tf(v.z), f2tf(v.w) };
            *(uint4*)&Bs[r * BSTR + bswz(r, c4 * 4)] = u;
        }
        __syncthreads();
        mma_stage(As, Bs, wm, wn, lane, acc);
        __syncthreads();
    }

    int g = lane >> 2, t = lane & 3;
    #pragma unroll
    for (int mt = 0; mt < 2; mt++) {
        int row = m0 + wm * 32 + mt * 16 + g;
        #pragma unroll
        for (int nt = 0; nt < 8; nt++) {
            int col = wn * 64 + nt * 8 + 2 * t;
            float bb0 = bias[col], bb1 = bias[col + 1];
            uint2 lo = { f2tf(acc[mt][nt][0] + bb0), f2tf(acc[mt][nt][1] + bb1) };
            uint2 hi = { f2tf(acc[mt][nt][2] + bb0), f2tf(acc[mt][nt][3] + bb1) };
            *(uint2*)(Out + (size_t)row * DH + col)       = lo;
            *(uint2*)(Out + (size_t)(row + 8) * DH + col) = hi;
        }
    }
}

// ===========================================================================
// scores: S = scale * Q·K^T  (raw, fp32) + per-(row, tile) max / exp-sum.
// ===========================================================================
__global__ __launch_bounds__(256, 2) void scores_kernel()
{
    __shared__ uint32_t As[128 * ASTR];
    __shared__ uint32_t Bs[32 * BSTR];
    __shared__ float redm[2][128];
    __shared__ float reds[2][128];

    int b  = blockIdx.z;
    int m0 = blockIdx.x * 128, n0 = blockIdx.y * 128;
    const uint32_t* Qb = (const uint32_t*)(g_q + (size_t)b * SEQ * DH);
    const uint32_t* Kb = (const uint32_t*)(g_k + (size_t)b * SEQ * DH);

    int tid = threadIdx.x;
    int lane = tid & 31, wid = tid >> 5;
    int wm = wid & 3, wn = wid >> 2;

    float acc[2][8][4];
    #pragma unroll
    for (int i = 0; i < 2; i++)
        #pragma unroll
        for (int j = 0; j < 8; j++)
            #pragma unroll
            for (int q = 0; q < 4; q++) acc[i][j][q] = 0.f;

    for (int k0 = 0; k0 < DH; k0 += 32) {
        #pragma unroll
        for (int it = 0; it < 4; it++) {
            int idx = tid + it * 256;
            int r = idx >> 3, c4 = idx & 7;
            *(uint4*)&As[r * ASTR + c4 * 4] =
                *(const uint4*)(Qb + (size_t)(m0 + r) * DH + k0 + c4 * 4);
        }
        #pragma unroll
        for (int it = 0; it < 4; it++) {      // B = K^T transpose-scatter
            int idx = tid + it * 256;
            int n = idx >> 3, c4 = idx & 7;
            uint4 u = *(const uint4*)(Kb + (size_t)(n0 + n) * DH + k0 + c4 * 4);
            int kk = c4 * 4;
            Bs[(kk + 0) * BSTR + bswz(kk + 0, n)] = u.x;
            Bs[(kk + 1) * BSTR + bswz(kk + 1, n)] = u.y;
            Bs[(kk + 2) * BSTR + bswz(kk + 2, n)] = u.z;
            Bs[(kk + 3) * BSTR + bswz(kk + 3, n)] = u.w;
        }
        __syncthreads();
        mma_stage(As, Bs, wm, wn, lane, acc);
        __syncthreads();
    }

    const float scale = 0.08838834764831845f;  // 1/sqrt(128)
    int g = lane >> 2, t = lane & 3;

    // scale in place, write raw S
    float* Pb = g_p + (size_t)b * SEQ * SEQ;
    #pragma unroll
    for (int mt = 0; mt < 2; mt++) {
        #pragma unroll
        for (int nt = 0; nt < 8; nt++)
            #pragma unroll
            for (int q = 0; q < 4; q++) acc[mt][nt][q] *= scale;
        int row = m0 + wm * 32 + mt * 16 + g;
        #pragma unroll
        for (int nt = 0; nt < 8; nt++) {
            int col = n0 + wn * 64 + nt * 8 + 2 * t;
            float2 lo = { acc[mt][nt][0], acc[mt][nt][1] };
            float2 hi = { acc[mt][nt][2], acc[mt][nt][3] };
            *(float2*)(Pb + (size_t)row * SEQ + col)       = lo;
            *(float2*)(Pb + (size_t)(row + 8) * SEQ + col) = hi;
        }
    }

    // per-(row, tile) max: reduce 16 vals/row/thread -> across t lanes -> across wn
    float rmax[2][2];
    #pragma unroll
    for (int mt = 0; mt < 2; mt++)
        #pragma unroll
        for (int h = 0; h < 2; h++) {
            float m = -1e30f;
            #pragma unroll
            for (int nt = 0; nt < 8; nt++)
                m = fmaxf(m, fmaxf(acc[mt][nt][h * 2], acc[mt][nt][h * 2 + 1]));
            m = fmaxf(m, __shfl_xor_sync(0xffffffffu, m, 1));
            m = fmaxf(m, __shfl_xor_sync(0xffffffffu, m, 2));
            if (t == 0) redm[wn][wm * 32 + mt * 16 + h * 8 + g] = m;
        }
    __syncthreads();

    #pragma unroll
    for (int mt = 0; mt < 2; mt++)
        #pragma unroll
        for (int h = 0; h < 2; h++) {
            int rl = wm * 32 + mt * 16 + h * 8 + g;
            float tm = fmaxf(redm[0][rl], redm[1][rl]);
            rmax[mt][h] = tm;
            float s = 0.f;
            #pragma unroll
            for (int nt = 0; nt < 8; nt++) {
                s += __expf(acc[mt][nt][h * 2]     - tm);
                s += __expf(acc[mt][nt][h * 2 + 1] - tm);
            }
            s += __shfl_xor_sync(0xffffffffu, s, 1);
            s += __shfl_xor_sync(0xffffffffu, s, 2);
            if (t == 0) reds[wn][rl] = s;
        }
    __syncthreads();

    if (wn == 0 && t == 0) {
        #pragma unroll
        for (int mt = 0; mt < 2; mt++)
            #pragma unroll
            for (int h = 0; h < 2; h++) {
                int rl = wm * 32 + mt * 16 + h * 8 + g;
                size_t gi = ((size_t)b * SEQ + m0 + rl) * NTILES + blockIdx.y;
                g_rmax[gi] = rmax[mt][h];
                g_rsum[gi] = reds[0][rl] + reds[1][rl];
            }
    }
}

// ===========================================================================
// stats: fold 16 per-tile (max, sum) into global row max and 1/sum.
// ===========================================================================
__global__ __launch_bounds__(256) void stats_kernel()
{
    int row = blockIdx.x * 256 + threadIdx.x;
    const float* mx = g_rmax + (size_t)row * NTILES;
    const float* sm = g_rsum + (size_t)row * NTILES;
    float M = -1e30f;
    #pragma unroll
    for (int i = 0; i < NTILES; i++) M = fmaxf(M, mx[i]);
    float s = 0.f;
    #pragma unroll
    for (int i = 0; i < NTILES; i++) s += sm[i] * __expf(mx[i] - M);
    g_rowm[row]   = M;
    g_rowinv[row] = 1.0f / s;
}

// ===========================================================================
// pv: O = softmax(S)·V with exp applied on A-tile loads.
// BM=64 -> grid 256 blocks -> 2 blocks/SM. 8 warps as 2(m) x 4(n).
// ===========================================================================
__global__ __launch_bounds__(256, 2) void pv_kernel(float* __restrict__ Out)
{
    __shared__ uint32_t As[64 * ASTR];
    __shared__ uint32_t Bs[32 * BSTR];

    int b  = blockIdx.y;
    int m0 = blockIdx.x * 64;
    const float*    Pb = g_p + (size_t)b * SEQ * SEQ;
    const uint32_t* Vb = (const uint32_t*)(g_v + (size_t)b * SEQ * DH);
    float*          Ob = Out + (size_t)b * SEQ * DH;

    int tid = threadIdx.x;
    int lane = tid & 31, wid = tid >> 5;
    int wm = wid & 1, wn = wid >> 1;

    // fixed A rows for this thread across all k chunks
    int ar0 = tid >> 3, ar1 = 32 + (tid >> 3);
    int ac4 = tid & 7;
    float m_0 = g_rowm[b * SEQ + m0 + ar0],  i_0 = g_rowinv[b * SEQ + m0 + ar0];
    float m_1 = g_rowm[b * SEQ + m0 + ar1],  i_1 = g_rowinv[b * SEQ + m0 + ar1];

    float acc[2][4][4];
    #pragma unroll
    for (int i = 0; i < 2; i++)
        #pragma unroll
        for (int j = 0; j < 4; j++)
            #pragma unroll
            for (int q = 0; q < 4; q++) acc[i][j][q] = 0.f;

    for (int k0 = 0; k0 < SEQ; k0 += 32) {
        {   // A = exp(S - m) * inv, rounded to tf32.  64x32 tile.
            float4 v0 = *(const float4*)(Pb + (size_t)(m0 + ar0) * SEQ + k0 + ac4 * 4);
            uint4 u0 = { f2tf(__expf(v0.x - m_0) * i_0), f2tf(__expf(v0.y - m_0) * i_0),
                         f2tf(__expf(v0.z - m_0) * i_0), f2tf(__expf(v0.w - m_0) * i_0) };
            *(uint4*)&As[ar0 * ASTR + ac4 * 4] = u0;
            float4 v1 = *(const float4*)(Pb + (size_t)(m0 + ar1) * SEQ + k0 + ac4 * 4);
            uint4 u1 = { f2tf(__expf(v1.x - m_1) * i_1), f2tf(__expf(v1.y - m_1) * i_1),
                         f2tf(__expf(v1.z - m_1) * i_1), f2tf(__expf(v1.w - m_1) * i_1) };
            *(uint4*)&As[ar1 * ASTR + ac4 * 4] = u1;
        }
        #pragma unroll
        for (int it = 0; it < 4; it++) {      // B = V rows 32x128 (pre-rounded)
            int idx = tid + it * 256;
            int r = idx >> 5, c4 = idx & 31;
            *(uint4*)&Bs[r * BSTR + bswz(r, c4 * 4)] =
                *(const uint4*)(Vb + (size_t)(k0 + r) * DH + c4 * 4);
        }
        __syncthreads();
        mma_stage64(As, Bs, wm, wn, lane, acc);
        __syncthreads();
    }

    int g = lane >> 2, t = lane & 3;
    #pragma unroll
    for (int mt = 0; mt < 2; mt++) {
        int row = m0 + wm * 32 + mt * 16 + g;
        #pragma unroll
        for (int nt = 0; nt < 4; nt++) {
            int col = wn * 32 + nt * 8 + 2 * t;
            float2 lo = { acc[mt][nt][0], acc[mt][nt][1] };
            float2 hi = { acc[mt][nt][2], acc[mt][nt][3] };
            *(float2*)(Ob + (size_t)row * DH + col)       = lo;
            *(float2*)(Ob + (size_t)(row + 8) * DH + col) = hi;
        }
    }
}

// ===========================================================================
extern "C" void kernel_launch(void* const* d_in, const int* in_sizes, int n_in,
                              void* d_out, int out_size)
{
    const float* q_in = (const float*)d_in[0];
    const float* k_in = (const float*)d_in[1];
    const float* v_in = (const float*)d_in[2];
    const float* Wq   = (const float*)d_in[3];
    const float* Wk   = (const float*)d_in[4];
    const float* Wv   = (const float*)d_in[5];
    const float* bq   = (const float*)d_in[6];
    const float* bk   = (const float*)d_in[7];
    const float* bv   = (const float*)d_in[8];
    float* out        = (float*)d_out;

    proj_kernel<<<dim3(MTOT / 128, 3), 256>>>(q_in, k_in, v_in, Wq, Wk, Wv, bq, bk, bv);
    scores_kernel<<<dim3(SEQ / 128, SEQ / 128, NB), 256>>>();
    stats_kernel<<<MTOT / 256, 256>>>();
    pv_kernel<<<dim3(SEQ / 64, NB), 256>>>(out);
}

// round 7
// speedup vs baseline: 2.4833x; 1.0217x over previous
#include <cuda_runtime.h>
#include <cstdint>

#define NB 8
#define SEQ 2048
#define DIN 512
#define DH 128
#define MTOT (NB*SEQ)
#define NTILES 16   // SEQ/128 column tiles per row

#define ASTR 36    // A smem row stride (u32): conflict-free frag loads
#define BSTR 136   // B smem row stride (u32)

// Scratch (device globals: allocation-free rule)
__device__ float g_q[MTOT*DH];
__device__ float g_k[MTOT*DH];
__device__ float g_v[MTOT*DH];
__device__ float g_p[(size_t)NB*SEQ*SEQ];   // raw scaled scores, 128 MB
__device__ float g_rmax[MTOT*NTILES];
__device__ float g_rsum[MTOT*NTILES];
__device__ float g_rowm[MTOT];
__device__ float g_rowinv[MTOT];

// ---------------------------------------------------------------------------
// helpers (baseline sm_80 ISA)
// ---------------------------------------------------------------------------
__device__ __forceinline__ uint32_t f2tf(float x) {
    uint32_t u;
    asm("cvt.rna.tf32.f32 %0, %1;" : "=r"(u) : "f"(x));
    return u;
}
__device__ __forceinline__ void mma8(float* c, const uint32_t* a, const uint32_t* b) {
    asm volatile(
        "mma.sync.aligned.m16n8k8.row.col.f32.tf32.tf32.f32 "
        "{%0,%1,%2,%3}, {%4,%5,%6,%7}, {%8,%9}, {%0,%1,%2,%3};"
        : "+f"(c[0]), "+f"(c[1]), "+f"(c[2]), "+f"(c[3])
        : "r"(a[0]), "r"(a[1]), "r"(a[2]), "r"(a[3]), "r"(b[0]), "r"(b[1]));
}
__device__ __forceinline__ int bswz(int k, int n) {
    return n ^ (((k >> 2) & 7) << 2);
}
__device__ __forceinline__ void cp16(void* dst, const void* src) {
    uint32_t d;
    asm("{ .reg .u64 t; cvta.to.shared.u64 t, %1; cvt.u32.u64 %0, t; }" : "=r"(d) : "l"(dst));
    asm volatile("cp.async.cg.shared.global [%0], [%1], 16;" :: "r"(d), "l"(src));
}
#define CP_COMMIT() asm volatile("cp.async.commit_group;" ::: "memory")
#define CP_WAIT1()  asm volatile("cp.async.wait_group 1;" ::: "memory")
#define CP_WAIT0()  asm volatile("cp.async.wait_group 0;" ::: "memory")

// BK=32 stage, BM=128/BN=128, B swizzled (proj): 8 warps 4(m) x 2(n).
__device__ __forceinline__ void mma_stage(const uint32_t* As, const uint32_t* Bs,
                                          int wm, int wn, int lane,
                                          float acc[2][8][4])
{
    int g = lane >> 2, t = lane & 3;
    #pragma unroll
    for (int s = 0; s < 4; s++) {
        int k8 = s * 8;
        uint32_t a[2][4], b[8][2];
        #pragma unroll
        for (int mt = 0; mt < 2; mt++) {
            int r = wm * 32 + mt * 16 + g;
            a[mt][0] = As[r * ASTR + k8 + t];
            a[mt][1] = As[(r + 8) * ASTR + k8 + t];
            a[mt][2] = As[r * ASTR + k8 + t + 4];
            a[mt][3] = As[(r + 8) * ASTR + k8 + t + 4];
        }
        #pragma unroll
        for (int nt = 0; nt < 8; nt++) {
            int c = wn * 64 + nt * 8 + g;
            b[nt][0] = Bs[(k8 + t) * BSTR + bswz(k8 + t, c)];
            b[nt][1] = Bs[(k8 + t + 4) * BSTR + bswz(k8 + t + 4, c)];
        }
        #pragma unroll
        for (int mt = 0; mt < 2; mt++)
            #pragma unroll
            for (int nt = 0; nt < 8; nt++)
                mma8(acc[mt][nt], a[mt], b[nt]);
    }
}

// BK=32 stage, BM=128/BN=128, B in NATURAL [n][k] layout stride ASTR (scores).
__device__ __forceinline__ void mma_stage_nat(const uint32_t* As, const uint32_t* Ks,
                                              int wm, int wn, int lane,
                                              float acc[2][8][4])
{
    int g = lane >> 2, t = lane & 3;
    #pragma unroll
    for (int s = 0; s < 4; s++) {
        int k8 = s * 8;
        uint32_t a[2][4], b[8][2];
        #pragma unroll
        for (int mt = 0; mt < 2; mt++) {
            int r = wm * 32 + mt * 16 + g;
            a[mt][0] = As[r * ASTR + k8 + t];
            a[mt][1] = As[(r + 8) * ASTR + k8 + t];
            a[mt][2] = As[r * ASTR + k8 + t + 4];
            a[mt][3] = As[(r + 8) * ASTR + k8 + t + 4];
        }
        #pragma unroll
        for (int nt = 0; nt < 8; nt++) {
            int c = wn * 64 + nt * 8 + g;
            b[nt][0] = Ks[c * ASTR + k8 + t];
            b[nt][1] = Ks[c * ASTR + k8 + t + 4];
        }
        #pragma unroll
        for (int mt = 0; mt < 2; mt++)
            #pragma unroll
            for (int nt = 0; nt < 8; nt++)
                mma8(acc[mt][nt], a[mt], b[nt]);
    }
}

// BK=32 stage, BM=64/BN=128, V in NATURAL [k][n] layout stride BSTR (pv).
__device__ __forceinline__ void mma_stage64v(const uint32_t* As, const uint32_t* Vs,
                                             int wm, int wn, int lane,
                                             float acc[2][4][4])
{
    int g = lane >> 2, t = lane & 3;
    #pragma unroll
    for (int s = 0; s < 4; s++) {
        int k8 = s * 8;
        uint32_t a[2][4], b[4][2];
        #pragma unroll
        for (int mt = 0; mt < 2; mt++) {
            int r = wm * 32 + mt * 16 + g;
            a[mt][0] = As[r * ASTR + k8 + t];
            a[mt][1] = As[(r + 8) * ASTR + k8 + t];
            a[mt][2] = As[r * ASTR + k8 + t + 4];
            a[mt][3] = As[(r + 8) * ASTR + k8 + t + 4];
        }
        #pragma unroll
        for (int nt = 0; nt < 4; nt++) {
            int c = wn * 32 + nt * 8 + g;
            b[nt][0] = Vs[(k8 + t) * BSTR + c];
            b[nt][1] = Vs[(k8 + t + 4) * BSTR + c];
        }
        #pragma unroll
        for (int mt = 0; mt < 2; mt++)
            #pragma unroll
            for (int nt = 0; nt < 4; nt++)
                mma8(acc[mt][nt], a[mt], b[nt]);
    }
}

// ===========================================================================
// Fused QKV projection via tf32 MMA (unchanged from round 6)
// ===========================================================================
__global__ __launch_bounds__(256, 2) void proj_kernel(
    const float* __restrict__ x0, const float* __restrict__ x1, const float* __restrict__ x2,
    const float* __restrict__ w0, const float* __restrict__ w1, const float* __restrict__ w2,
    const float* __restrict__ b0, const float* __restrict__ b1, const float* __restrict__ b2)
{
    __shared__ uint32_t As[128 * ASTR];
    __shared__ uint32_t Bs[32 * BSTR];

    int sel = blockIdx.y;
    const float* X    = sel == 0 ? x0 : (sel == 1 ? x1 : x2);
    const float* W    = sel == 0 ? w0 : (sel == 1 ? w1 : w2);
    const float* bias = sel == 0 ? b0 : (sel == 1 ? b1 : b2);
    float*       Out  = sel == 0 ? g_q : (sel == 1 ? g_k : g_v);

    int m0  = blockIdx.x * 128;
    int tid = threadIdx.x;
    int lane = tid & 31, wid = tid >> 5;
    int wm = wid & 3, wn = wid >> 2;

    float acc[2][8][4];
    #pragma unroll
    for (int i = 0; i < 2; i++)
        #pragma unroll
        for (int j = 0; j < 8; j++)
            #pragma unroll
            for (int q = 0; q < 4; q++) acc[i][j][q] = 0.f;

    for (int k0 = 0; k0 < DIN; k0 += 32) {
        #pragma unroll
        for (int it = 0; it < 4; it++) {
            int idx = tid + it * 256;
            int r = idx >> 3, c4 = idx & 7;
            float4 v = *(const float4*)(X + (size_t)(m0 + r) * DIN + k0 + c4 * 4);
            uint4 u = { f2tf(v.x), f2tf(v.y), f2tf(v.z), f2tf(v.w) };
            *(uint4*)&As[r * ASTR + c4 * 4] = u;
        }
        #pragma unroll
        for (int it = 0; it < 4; it++) {
            int idx = tid + it * 256;
            int r = idx >> 5, c4 = idx & 31;
            float4 v = *(const float4*)(W + (size_t)(k0 + r) * DH + c4 * 4);
            uint4 u = { f2tf(v.x), f2tf(v.y), f2tf(v.z), f2tf(v.w) };
            *(uint4*)&Bs[r * BSTR + bswz(r, c4 * 4)] = u;
        }
        __syncthreads();
        mma_stage(As, Bs, wm, wn, lane, acc);
        __syncthreads();
    }

    int g = lane >> 2, t = lane & 3;
    #pragma unroll
    for (int mt = 0; mt < 2; mt++) {
        int row = m0 + wm * 32 + mt * 16 + g;
        #pragma unroll
        for (int nt = 0; nt < 8; nt++) {
            int col = wn * 64 + nt * 8 + 2 * t;
            float bb0 = bias[col], bb1 = bias[col + 1];
            uint2 lo = { f2tf(acc[mt][nt][0] + bb0), f2tf(acc[mt][nt][1] + bb1) };
            uint2 hi = { f2tf(acc[mt][nt][2] + bb0), f2tf(acc[mt][nt][3] + bb1) };
            *(uint2*)(Out + (size_t)row * DH + col)       = lo;
            *(uint2*)(Out + (size_t)(row + 8) * DH + col) = hi;
        }
    }
}

// ===========================================================================
// scores: cp.async double-buffered, K in natural layout.
// Dynamic smem: A[2] (128*36), K[2] (128*36), redm[256], reds[256].
// ===========================================================================
#define SC_A0   0
#define SC_A1   4608
#define SC_K0   9216
#define SC_K1   13824
#define SC_RED  18432
#define SC_SMEM ((18432 + 512) * 4)

__global__ __launch_bounds__(256, 2) void scores_kernel()
{
    extern __shared__ uint32_t ds[];
    uint32_t* Ab[2] = { ds + SC_A0, ds + SC_A1 };
    uint32_t* Kb2[2] = { ds + SC_K0, ds + SC_K1 };
    float* redm = (float*)(ds + SC_RED);        // [2][128]
    float* reds = (float*)(ds + SC_RED + 256);  // [2][128]

    int b  = blockIdx.z;
    int m0 = blockIdx.x * 128, n0 = blockIdx.y * 128;
    const float* Qb = g_q + (size_t)b * SEQ * DH;
    const float* Kg = g_k + (size_t)b * SEQ * DH;

    int tid = threadIdx.x;
    int lane = tid & 31, wid = tid >> 5;
    int wm = wid & 3, wn = wid >> 2;

    float acc[2][8][4];
    #pragma unroll
    for (int i = 0; i < 2; i++)
        #pragma unroll
        for (int j = 0; j < 8; j++)
            #pragma unroll
            for (int q = 0; q < 4; q++) acc[i][j][q] = 0.f;

    int lr = tid >> 3, lc4 = tid & 7;   // per-thread copy slots (4 iters of 256)

    // prologue: chunk 0
    #pragma unroll
    for (int it = 0; it < 4; it++) {
        int idx = tid + it * 256;
        int r = idx >> 3, c4 = idx & 7;
        cp16(&Ab[0][r * ASTR + c4 * 4], Qb + (size_t)(m0 + r) * DH + c4 * 4);
        cp16(&Kb2[0][r * ASTR + c4 * 4], Kg + (size_t)(n0 + r) * DH + c4 * 4);
    }
    CP_COMMIT();

    for (int i = 0; i < 4; i++) {
        int cur = i & 1;
        if (i < 3) {
            int k1 = (i + 1) * 32;
            #pragma unroll
            for (int it = 0; it < 4; it++) {
                int idx = tid + it * 256;
                int r = idx >> 3, c4 = idx & 7;
                cp16(&Ab[cur ^ 1][r * ASTR + c4 * 4], Qb + (size_t)(m0 + r) * DH + k1 + c4 * 4);
                cp16(&Kb2[cur ^ 1][r * ASTR + c4 * 4], Kg + (size_t)(n0 + r) * DH + k1 + c4 * 4);
            }
            CP_COMMIT();
            CP_WAIT1();
        } else {
            CP_WAIT0();
        }
        __syncthreads();
        mma_stage_nat(Ab[cur], Kb2[cur], wm, wn, lane, acc);
        __syncthreads();
    }
    (void)lr; (void)lc4;

    const float scale = 0.08838834764831845f;  // 1/sqrt(128)
    int g = lane >> 2, t = lane & 3;

    float* Pb = g_p + (size_t)b * SEQ * SEQ;
    #pragma unroll
    for (int mt = 0; mt < 2; mt++) {
        #pragma unroll
        for (int nt = 0; nt < 8; nt++)
            #pragma unroll
            for (int q = 0; q < 4; q++) acc[mt][nt][q] *= scale;
        int row = m0 + wm * 32 + mt * 16 + g;
        #pragma unroll
        for (int nt = 0; nt < 8; nt++) {
            int col = n0 + wn * 64 + nt * 8 + 2 * t;
            float2 lo = { acc[mt][nt][0], acc[mt][nt][1] };
            float2 hi = { acc[mt][nt][2], acc[mt][nt][3] };
            *(float2*)(Pb + (size_t)row * SEQ + col)       = lo;
            *(float2*)(Pb + (size_t)(row + 8) * SEQ + col) = hi;
        }
    }

    // per-(row, tile) max / exp-sum
    float rmax[2][2];
    #pragma unroll
    for (int mt = 0; mt < 2; mt++)
        #pragma unroll
        for (int h = 0; h < 2; h++) {
            float m = -1e30f;
            #pragma unroll
            for (int nt = 0; nt < 8; nt++)
                m = fmaxf(m, fmaxf(acc[mt][nt][h * 2], acc[mt][nt][h * 2 + 1]));
            m = fmaxf(m, __shfl_xor_sync(0xffffffffu, m, 1));
            m = fmaxf(m, __shfl_xor_sync(0xffffffffu, m, 2));
            if (t == 0) redm[wn * 128 + wm * 32 + mt * 16 + h * 8 + g] = m;
        }
    __syncthreads();

    #pragma unroll
    for (int mt = 0; mt < 2; mt++)
        #pragma unroll
        for (int h = 0; h < 2; h++) {
            int rl = wm * 32 + mt * 16 + h * 8 + g;
            float tm = fmaxf(redm[rl], redm[128 + rl]);
            rmax[mt][h] = tm;
            float s = 0.f;
            #pragma unroll
            for (int nt = 0; nt < 8; nt++) {
                s += __expf(acc[mt][nt][h * 2]     - tm);
                s += __expf(acc[mt][nt][h * 2 + 1] - tm);
            }
            s += __shfl_xor_sync(0xffffffffu, s, 1);
            s += __shfl_xor_sync(0xffffffffu, s, 2);
            if (t == 0) reds[wn * 128 + rl] = s;
        }
    __syncthreads();

    if (wn == 0 && t == 0) {
        #pragma unroll
        for (int mt = 0; mt < 2; mt++)
            #pragma unroll
            for (int h = 0; h < 2; h++) {
                int rl = wm * 32 + mt * 16 + h * 8 + g;
                size_t gi = ((size_t)b * SEQ + m0 + rl) * NTILES + blockIdx.y;
                g_rmax[gi] = rmax[mt][h];
                g_rsum[gi] = reds[rl] + reds[128 + rl];
            }
    }
}

// ===========================================================================
// stats: fold 16 per-tile (max, sum) into global row max and 1/sum.
// ===========================================================================
__global__ __launch_bounds__(256) void stats_kernel()
{
    int row = blockIdx.x * 256 + threadIdx.x;
    const float* mx = g_rmax + (size_t)row * NTILES;
    const float* sm = g_rsum + (size_t)row * NTILES;
    float M = -1e30f;
    #pragma unroll
    for (int i = 0; i < NTILES; i++) M = fmaxf(M, mx[i]);
    float s = 0.f;
    #pragma unroll
    for (int i = 0; i < NTILES; i++) s += sm[i] * __expf(mx[i] - M);
    g_rowm[row]   = M;
    g_rowinv[row] = 1.0f / s;
}

// ===========================================================================
// pv: cp.async staged S + V double buffers. BM=64, 8 warps 2(m) x 4(n).
// Dynamic smem: Amma (64*36), Sraw[2] (64*36), V[2] (32*136).
// ===========================================================================
#define PV_AMMA 0
#define PV_S0   2304
#define PV_S1   4608
#define PV_V0   6912
#define PV_V1   11264
#define PV_SMEM (15616 * 4)

__global__ __launch_bounds__(256, 2) void pv_kernel(float* __restrict__ Out)
{
    extern __shared__ uint32_t ds[];
    uint32_t* Amma  = ds + PV_AMMA;
    uint32_t* Sr[2] = { ds + PV_S0, ds + PV_S1 };
    uint32_t* Vs[2] = { ds + PV_V0, ds + PV_V1 };

    int b  = blockIdx.y;
    int m0 = blockIdx.x * 64;
    const float* Pb = g_p + (size_t)b * SEQ * SEQ;
    const float* Vg = g_v + (size_t)b * SEQ * DH;
    float*       Ob = Out + (size_t)b * SEQ * DH;

    int tid = threadIdx.x;
    int lane = tid & 31, wid = tid >> 5;
    int wm = wid & 1, wn = wid >> 1;

    int ar0 = tid >> 3, ar1 = 32 + (tid >> 3);
    int ac4 = tid & 7;
    float m_0 = g_rowm[b * SEQ + m0 + ar0],  i_0 = g_rowinv[b * SEQ + m0 + ar0];
    float m_1 = g_rowm[b * SEQ + m0 + ar1],  i_1 = g_rowinv[b * SEQ + m0 + ar1];

    float acc[2][4][4];
    #pragma unroll
    for (int i = 0; i < 2; i++)
        #pragma unroll
        for (int j = 0; j < 4; j++)
            #pragma unroll
            for (int q = 0; q < 4; q++) acc[i][j][q] = 0.f;

    // prologue: chunk 0
    cp16(&Sr[0][ar0 * ASTR + ac4 * 4], Pb + (size_t)(m0 + ar0) * SEQ + ac4 * 4);
    cp16(&Sr[0][ar1 * ASTR + ac4 * 4], Pb + (size_t)(m0 + ar1) * SEQ + ac4 * 4);
    #pragma unroll
    for (int it = 0; it < 4; it++) {
        int idx = tid + it * 256;
        int r = idx >> 5, c4 = idx & 31;
        cp16(&Vs[0][r * BSTR + c4 * 4], Vg + (size_t)r * DH + c4 * 4);
    }
    CP_COMMIT();

    for (int i = 0; i < SEQ / 32; i++) {
        int cur = i & 1;
        if (i < SEQ / 32 - 1) {
            int k1 = (i + 1) * 32;
            cp16(&Sr[cur ^ 1][ar0 * ASTR + ac4 * 4], Pb + (size_t)(m0 + ar0) * SEQ + k1 + ac4 * 4);
            cp16(&Sr[cur ^ 1][ar1 * ASTR + ac4 * 4], Pb + (size_t)(m0 + ar1) * SEQ + k1 + ac4 * 4);
            #pragma unroll
            for (int it = 0; it < 4; it++) {
                int idx = tid + it * 256;
                int r = idx >> 5, c4 = idx & 31;
                cp16(&Vs[cur ^ 1][r * BSTR + c4 * 4], Vg + (size_t)(k1 + r) * DH + c4 * 4);
            }
            CP_COMMIT();
            CP_WAIT1();
        } else {
            CP_WAIT0();
        }
        // transform own staged S words -> Amma (no barrier needed before this:
        // each thread reads exactly the addresses it cp.async'd, completion
        // guaranteed by wait_group above; Amma anti-dep covered by tail sync)
        {
            float4 v0 = *(const float4*)&Sr[cur][ar0 * ASTR + ac4 * 4];
            uint4 u0 = { f2tf(__expf(v0.x - m_0) * i_0), f2tf(__expf(v0.y - m_0) * i_0),
                         f2tf(__expf(v0.z - m_0) * i_0), f2tf(__expf(v0.w - m_0) * i_0) };
            *(uint4*)&Amma[ar0 * ASTR + ac4 * 4] = u0;
            float4 v1 = *(const float4*)&Sr[cur][ar1 * ASTR + ac4 * 4];
            uint4 u1 = { f2tf(__expf(v1.x - m_1) * i_1), f2tf(__expf(v1.y - m_1) * i_1),
                         f2tf(__expf(v1.z - m_1) * i_1), f2tf(__expf(v1.w - m_1) * i_1) };
            *(uint4*)&Amma[ar1 * ASTR + ac4 * 4] = u1;
        }
        __syncthreads();
        mma_stage64v(Amma, Vs[cur], wm, wn, lane, acc);
        __syncthreads();
    }

    int g = lane >> 2, t = lane & 3;
    #pragma unroll
    for (int mt = 0; mt < 2; mt++) {
        int row = m0 + wm * 32 + mt * 16 + g;
        #pragma unroll
        for (int nt = 0; nt < 4; nt++) {
            int col = wn * 32 + nt * 8 + 2 * t;
            float2 lo = { acc[mt][nt][0], acc[mt][nt][1] };
            float2 hi = { acc[mt][nt][2], acc[mt][nt][3] };
            *(float2*)(Ob + (size_t)row * DH + col)       = lo;
            *(float2*)(Ob + (size_t)(row + 8) * DH + col) = hi;
        }
    }
}

// ===========================================================================
extern "C" void kernel_launch(void* const* d_in, const int* in_sizes, int n_in,
                              void* d_out, int out_size)
{
    const float* q_in = (const float*)d_in[0];
    const float* k_in = (const float*)d_in[1];
    const float* v_in = (const float*)d_in[2];
    const float* Wq   = (const float*)d_in[3];
    const float* Wk   = (const float*)d_in[4];
    const float* Wv   = (const float*)d_in[5];
    const float* bq   = (const float*)d_in[6];
    const float* bk   = (const float*)d_in[7];
    const float* bv   = (const float*)d_in[8];
    float* out        = (float*)d_out;

    static bool attr_done = false;
    if (!attr_done) {
        cudaFuncSetAttribute(scores_kernel, cudaFuncAttributeMaxDynamicSharedMemorySize, SC_SMEM);
        cudaFuncSetAttribute(pv_kernel,     cudaFuncAttributeMaxDynamicSharedMemorySize, PV_SMEM);
        attr_done = true;
    }

    proj_kernel<<<dim3(MTOT / 128, 3), 256>>>(q_in, k_in, v_in, Wq, Wk, Wv, bq, bk, bv);
    scores_kernel<<<dim3(SEQ / 128, SEQ / 128, NB), 256, SC_SMEM>>>();
    stats_kernel<<<MTOT / 256, 256>>>();
    pv_kernel<<<dim3(SEQ / 64, NB), 256, PV_SMEM>>>(out);
}